// round 1
// baseline (speedup 1.0000x reference)
#include <cuda_runtime.h>

// CRF NLL: B=1024, T=512, C=53, BOS=1, EOS=2
// inputs: d_in[0]=emissions f32 [B,T,C], d_in[1]=tags i32 [B,T],
//         d_in[2]=mask f32 [B,T], d_in[3]=transitions f32 [C,C]
// output: scalar f32 = sum_b (partition_b - score_b)

#define Bn   1024
#define Tn   512
#define Cn   53
#define BOSi 1
#define EOSi 2
#define NTH  64

__device__ float g_partial[Bn];

__global__ void __launch_bounds__(NTH)
crf_fwd_kernel(const float* __restrict__ em,
               const int*   __restrict__ tags,
               const float* __restrict__ mask,
               const float* __restrict__ trans)
{
    __shared__ float trs[Cn * Cn];   // transitions
    __shared__ float p_sm[NTH];      // rescaled alpha probs
    __shared__ float wred[6];        // cross-warp reduction scratch

    const int tid  = threadIdx.x;
    const int b    = blockIdx.x;
    const int lane = tid & 31;
    const int wid  = tid >> 5;

    // stage transitions in smem (needed for scores gather + init/final terms)
    for (int i = tid; i < Cn * Cn; i += NTH) trs[i] = trans[i];
    __syncthreads();

    const bool act = (tid < Cn);
    const int  cc  = act ? tid : (Cn - 1);
    const float NEG = -1e30f;

    // per-thread register column: ecol[c] = exp(Tr[c, cc])
    float ecol[Cn];
#pragma unroll
    for (int c = 0; c < Cn; c++) ecol[c] = __expf(trs[c * Cn + cc]);

    // alphas0 = Tr[BOS,:] + emissions[b,1,:]
    float alpha = act ? (trs[BOSi * Cn + tid] + em[(b * Tn + 1) * Cn + tid]) : NEG;

    int tlen = Tn - 1;  // fallback (lengths < T always, so break will fire)

    for (int t = 2; t < Tn; t++) {
        float m = mask[b * Tn + t];          // uniform across block
        if (m == 0.0f) { tlen = t; break; }  // mask is monotone -> t == length

        // block max of alpha
        float v = alpha;
#pragma unroll
        for (int off = 16; off; off >>= 1)
            v = fmaxf(v, __shfl_xor_sync(0xffffffffu, v, off));
        if (lane == 0) wred[wid] = v;
        __syncthreads();
        float M = fmaxf(wred[0], wred[1]);

        // p_c = exp(alpha_c - M)  (inactive threads contribute exp(-inf)=0)
        p_sm[tid] = __expf(alpha - M);
        __syncthreads();

        // new_cc = M + log( sum_c p_c * exp(Tr[c,cc]) ) + em[b,t,cc]
        float acc = 0.0f;
#pragma unroll
        for (int c = 0; c < Cn; c++) acc = fmaf(p_sm[c], ecol[c], acc);

        float e  = em[(b * Tn + t) * Cn + cc];
        float na = M + __logf(acc) + e;
        alpha = act ? na : NEG;
        // no extra sync needed: next iteration's wred write is gated by this
        // iteration's __syncthreads() pair (see analysis), p_sm likewise.
    }

    // partition = logsumexp(alpha + Tr[:,EOS])
    float fv = act ? (alpha + trs[tid * Cn + EOSi]) : NEG;
    float v = fv;
#pragma unroll
    for (int off = 16; off; off >>= 1)
        v = fmaxf(v, __shfl_xor_sync(0xffffffffu, v, off));
    if (lane == 0) wred[wid] = v;
    __syncthreads();
    float M2 = fmaxf(wred[0], wred[1]);

    float ex = __expf(fv - M2);
#pragma unroll
    for (int off = 16; off; off >>= 1)
        ex += __shfl_xor_sync(0xffffffffu, ex, off);
    if (lane == 0) wred[2 + wid] = ex;
    __syncthreads();
    float partition = M2 + __logf(wred[2] + wred[3]);

    // ---- scores (gold path) ----
    // sum over t in [2, tlen): em[b,t,tags[t]] + Tr[tags[t-1], tags[t]]
    float s = 0.0f;
    for (int t = 2 + tid; t < tlen; t += NTH) {
        int tg = tags[b * Tn + t];
        int tp = tags[b * Tn + t - 1];
        s += em[(b * Tn + t) * Cn + tg] + trs[tp * Cn + tg];
    }
#pragma unroll
    for (int off = 16; off; off >>= 1)
        s += __shfl_xor_sync(0xffffffffu, s, off);
    if (lane == 0) wred[4 + wid] = s;
    __syncthreads();

    if (tid == 0) {
        float s_tot = wred[4] + wred[5];
        int   tg1   = tags[b * Tn + 1];
        float first = trs[BOSi * Cn + tg1] + em[(b * Tn + 1) * Cn + tg1];
        int   lt    = tags[b * Tn + tlen];  // last_tags = tags[b, length]
        float score = first + s_tot + trs[lt * Cn + EOSi];
        g_partial[b] = partition - score;
    }
}

__global__ void __launch_bounds__(512)
crf_reduce_kernel(float* __restrict__ out)
{
    __shared__ float sm[512];
    int tid = threadIdx.x;
    sm[tid] = g_partial[tid] + g_partial[tid + 512];
    __syncthreads();
#pragma unroll
    for (int s = 256; s > 0; s >>= 1) {
        if (tid < s) sm[tid] += sm[tid + s];
        __syncthreads();
    }
    if (tid == 0) out[0] = sm[0];
}

extern "C" void kernel_launch(void* const* d_in, const int* in_sizes, int n_in,
                              void* d_out, int out_size)
{
    const float* em    = (const float*)d_in[0];
    const int*   tags  = (const int*)  d_in[1];
    const float* mask  = (const float*)d_in[2];
    const float* trans = (const float*)d_in[3];
    float* out = (float*)d_out;

    crf_fwd_kernel<<<Bn, NTH>>>(em, tags, mask, trans);
    crf_reduce_kernel<<<1, 512>>>(out);
}

// round 2
// speedup vs baseline: 1.8774x; 1.8774x over previous
#include <cuda_runtime.h>

// CRF NLL: B=1024, T=512, C=53, BOS=1, EOS=2
// Scaled-probability forward recurrence, one warp per batch,
// packed f32x2 FMA mat-vec, renormalize-by-p[0] every 2 steps.

#define Bn   1024
#define Tn   512
#define Cn   53
#define BOSi 1
#define EOSi 2

__device__ float g_partial[Bn];

__device__ __forceinline__ unsigned long long pack2(float a, float b) {
    unsigned long long r;
    asm("mov.b64 %0, {%1,%2};" : "=l"(r) : "f"(a), "f"(b));
    return r;
}
__device__ __forceinline__ void unpack2(unsigned long long v, float& a, float& b) {
    asm("mov.b64 {%0,%1}, %2;" : "=f"(a), "=f"(b) : "l"(v));
}
__device__ __forceinline__ void fma2(unsigned long long& acc,
                                     unsigned long long a, unsigned long long b) {
    asm("fma.rn.f32x2 %0, %1, %2, %0;" : "+l"(acc) : "l"(a), "l"(b));
}
__device__ __forceinline__ unsigned long long add2(unsigned long long a,
                                                   unsigned long long b) {
    unsigned long long r;
    asm("add.rn.f32x2 %0, %1, %2;" : "=l"(r) : "l"(a), "l"(b));
    return r;
}
__device__ __forceinline__ void lds_v2u64(unsigned addr,
                                          unsigned long long& x, unsigned long long& y) {
    asm volatile("ld.shared.v2.u64 {%0,%1}, [%2];" : "=l"(x), "=l"(y) : "r"(addr));
}

__global__ void __launch_bounds__(64)
crf_fwd_kernel(const float* __restrict__ em,
               const int*   __restrict__ tags,
               const float* __restrict__ mask,
               const float* __restrict__ trans)
{
    __shared__ float trs[Cn * Cn];
    __shared__ __align__(16) float p_sm[2][2][64];  // [warp][buf][slot]

    const int tid  = threadIdx.x;
    const int lane = tid & 31;
    const int w    = tid >> 5;
    const int b    = blockIdx.x * 2 + w;

    for (int i = tid; i < Cn * Cn; i += 64) trs[i] = trans[i];
    __syncthreads();

    const int  c0  = 2 * lane, c1 = 2 * lane + 1;
    const bool okA = (c0 < Cn), okB = (c1 < Cn);
    const float* emb = em + (size_t)b * Tn * Cn;
    const int*   tg  = tags + b * Tn;

    // ---- sequence length = sum(mask) ----
    float ms = 0.f;
    for (int i = lane; i < Tn; i += 32) ms += mask[b * Tn + i];
#pragma unroll
    for (int off = 16; off; off >>= 1) ms += __shfl_xor_sync(~0u, ms, off);
    const int tlen = (int)ms;

    // ---- packed exp(transition) columns: eA/eB[k] = (E[2k][c], E[2k+1][c]) ----
    unsigned long long eA[28], eB[28];
#pragma unroll
    for (int k = 0; k < 28; k++) {
        int r0 = 2 * k, r1 = 2 * k + 1;
        float a0 = 0.f, a1 = 0.f, b0 = 0.f, b1 = 0.f;
        if (okA && r0 < Cn) a0 = __expf(trs[r0 * Cn + c0]);
        if (okA && r1 < Cn) a1 = __expf(trs[r1 * Cn + c0]);
        if (okB && r0 < Cn) b0 = __expf(trs[r0 * Cn + c1]);
        if (okB && r1 < Cn) b1 = __expf(trs[r1 * Cn + c1]);
        eA[k] = pack2(a0, a1);
        eB[k] = pack2(b0, b1);
    }

    // ---- init: p = exp(T[BOS,c] + em[b,1,c]), L = 0 ----
    float p0 = 0.f, p1 = 0.f;
    if (okA) p0 = __expf(trs[BOSi * Cn + c0] + emb[Cn + c0]);
    if (okB) p1 = __expf(trs[BOSi * Cn + c1] + emb[Cn + c1]);
    int buf = 0;
    *(float2*)&p_sm[w][0][c0] = make_float2(p0, p1);
    __syncwarp();

    const unsigned pbase = (unsigned)__cvta_generic_to_shared(&p_sm[w][0][0]);

    // emission prefetch pipeline: (cur = t, nxt = t+1)
    float e0c = 0.f, e1c = 0.f, e0n = 0.f, e1n = 0.f;
    if (okA) e0c = emb[2 * Cn + c0];
    if (okB) e1c = emb[2 * Cn + c1];
    if (okA) e0n = emb[3 * Cn + c0];
    if (okB) e1n = emb[3 * Cn + c1];

    float L = 0.f;
    for (int t = 2; t < tlen; t++) {
        // prefetch t+2 (clamped row; value unused past tlen)
        int tp = t + 2; if (tp > Tn - 1) tp = Tn - 1;
        float e0f = 0.f, e1f = 0.f;
        if (okA) e0f = emb[tp * Cn + c0];
        if (okB) e1f = emb[tp * Cn + c1];

        // mat-vec: acc_c' = sum_c p_c * exp(T[c,c'])  (packed pairs)
        unsigned pa = pbase + (unsigned)buf * 256u;
        unsigned long long accA0 = 0, accA1 = 0, accB0 = 0, accB1 = 0;
#pragma unroll
        for (int k = 0; k < 14; k++) {
            unsigned long long x, y;
            lds_v2u64(pa + 16u * k, x, y);
            fma2(accA0, x, eA[2 * k]);
            fma2(accA1, y, eA[2 * k + 1]);
            fma2(accB0, x, eB[2 * k]);
            fma2(accB1, y, eB[2 * k + 1]);
        }
        float sA, sB;
        {
            float u, v;
            unpack2(add2(accA0, accA1), u, v); sA = u + v;
            unpack2(add2(accB0, accB1), u, v); sB = u + v;
        }

        // renormalize every 2 steps by p_prev[0] (single broadcast read)
        float r = 1.0f;
        if (!(t & 1)) {
            float s = p_sm[w][buf][0];
            r = __fdividef(1.0f, s);
            L += __logf(s);
        }

        float np0 = sA * r * __expf(e0c);
        float np1 = sB * r * __expf(e1c);
        buf ^= 1;
        *(float2*)&p_sm[w][buf][c0] = make_float2(np0, np1);
        __syncwarp();

        p0 = np0; p1 = np1;
        e0c = e0n; e1c = e1n; e0n = e0f; e1n = e1f;
    }

    // ---- partition = L + log( sum_c p_c * exp(T[c,EOS]) ) ----
    float fA = 0.f, fB = 0.f;
    if (okA) fA = p0 * __expf(trs[c0 * Cn + EOSi]);
    if (okB) fB = p1 * __expf(trs[c1 * Cn + EOSi]);
    float tot = fA + fB;
#pragma unroll
    for (int off = 16; off; off >>= 1) tot += __shfl_xor_sync(~0u, tot, off);
    float partition = L + __logf(tot);

    // ---- gold-path score ----
    float s = 0.f;
    for (int t = 2 + lane; t < tlen; t += 32) {
        int a = tg[t - 1], c = tg[t];
        s += emb[t * Cn + c] + trs[a * Cn + c];
    }
#pragma unroll
    for (int off = 16; off; off >>= 1) s += __shfl_xor_sync(~0u, s, off);

    if (lane == 0) {
        int   t1    = tg[1];
        float first = trs[BOSi * Cn + t1] + emb[Cn + t1];
        int   lt    = tg[tlen];  // reference uses tags at index == length
        float score = first + s + trs[lt * Cn + EOSi];
        g_partial[b] = partition - score;
    }
}

__global__ void __launch_bounds__(512)
crf_reduce_kernel(float* __restrict__ out)
{
    __shared__ float sm[512];
    int tid = threadIdx.x;
    sm[tid] = g_partial[tid] + g_partial[tid + 512];
    __syncthreads();
#pragma unroll
    for (int s = 256; s > 0; s >>= 1) {
        if (tid < s) sm[tid] += sm[tid + s];
        __syncthreads();
    }
    if (tid == 0) out[0] = sm[0];
}

extern "C" void kernel_launch(void* const* d_in, const int* in_sizes, int n_in,
                              void* d_out, int out_size)
{
    const float* em    = (const float*)d_in[0];
    const int*   tags  = (const int*)  d_in[1];
    const float* mask  = (const float*)d_in[2];
    const float* trans = (const float*)d_in[3];
    float* out = (float*)d_out;

    crf_fwd_kernel<<<Bn / 2, 64>>>(em, tags, mask, trans);
    crf_reduce_kernel<<<1, 512>>>(out);
}

// round 3
// speedup vs baseline: 2.0552x; 1.0947x over previous
#include <cuda_runtime.h>

// CRF NLL: B=1024, T=512, C=53, BOS=1, EOS=2
// Scaled-probability forward recurrence, one warp per batch,
// packed f32x2 FMA mat-vec, 4-step chunked emission prefetch,
// renorm every 4 steps, fused last-block reduction.

#define Bn   1024
#define Tn   512
#define Cn   53
#define BOSi 1
#define EOSi 2

__device__ float    g_partial[Bn];
__device__ unsigned g_ticket;   // zero-init; reset by last block each launch

__device__ __forceinline__ unsigned long long pack2(float a, float b) {
    unsigned long long r;
    asm("mov.b64 %0, {%1,%2};" : "=l"(r) : "f"(a), "f"(b));
    return r;
}
__device__ __forceinline__ void unpack2(unsigned long long v, float& a, float& b) {
    asm("mov.b64 {%0,%1}, %2;" : "=f"(a), "=f"(b) : "l"(v));
}
__device__ __forceinline__ void fma2(unsigned long long& acc,
                                     unsigned long long a, unsigned long long b) {
    asm("fma.rn.f32x2 %0, %1, %2, %0;" : "+l"(acc) : "l"(a), "l"(b));
}
__device__ __forceinline__ unsigned long long add2(unsigned long long a,
                                                   unsigned long long b) {
    unsigned long long r;
    asm("add.rn.f32x2 %0, %1, %2;" : "=l"(r) : "l"(a), "l"(b));
    return r;
}
__device__ __forceinline__ void lds_v2u64(unsigned addr,
                                          unsigned long long& x, unsigned long long& y) {
    asm volatile("ld.shared.v2.u64 {%0,%1}, [%2];" : "=l"(x), "=l"(y) : "r"(addr));
}

// one forward step: dot (p . expT), optional renorm, scale by exp(emission), store
#define CRF_STEP(E0, E1, REN) do {                                          \
    unsigned pa_ = pbase + (unsigned)buf * 256u;                            \
    unsigned long long aA0=0, aA1=0, aB0=0, aB1=0;                          \
    _Pragma("unroll")                                                       \
    for (int k_ = 0; k_ < 14; k_++) {                                       \
        unsigned long long x_, y_;                                          \
        lds_v2u64(pa_ + 16u * k_, x_, y_);                                  \
        fma2(aA0, x_, eA[2*k_]);  fma2(aA1, y_, eA[2*k_+1]);                \
        fma2(aB0, x_, eB[2*k_]);  fma2(aB1, y_, eB[2*k_+1]);                \
    }                                                                       \
    float u_, v_, sA_, sB_;                                                 \
    unpack2(add2(aA0, aA1), u_, v_); sA_ = u_ + v_;                         \
    unpack2(add2(aB0, aB1), u_, v_); sB_ = u_ + v_;                         \
    float r_ = 1.0f;                                                        \
    if (REN) {                                                              \
        float s_ = p_row[buf * 64];                                         \
        r_ = __fdividef(1.0f, s_);                                          \
        L += __logf(s_);                                                    \
    }                                                                       \
    float n0_ = sA_ * r_ * __expf(E0);                                      \
    float n1_ = sB_ * r_ * __expf(E1);                                      \
    buf ^= 1;                                                               \
    *(float2*)(p_row + buf * 64 + 2 * lane) = make_float2(n0_, n1_);        \
    __syncwarp();                                                           \
    p0 = n0_; p1 = n1_;                                                     \
} while (0)

// burst-load 4 steps of emissions (rows BASEROW..BASEROW+3, clamped)
#define LOADCHUNK(P0, P1, BASEROW) do {                                     \
    _Pragma("unroll")                                                       \
    for (int j_ = 0; j_ < 4; j_++) {                                        \
        int rr_ = (BASEROW) + j_; if (rr_ > Tn - 1) rr_ = Tn - 1;           \
        const float* rp_ = emb + (size_t)rr_ * Cn;                          \
        P0[j_] = okA ? __ldg(rp_ + c0) : 0.0f;                              \
        P1[j_] = okB ? __ldg(rp_ + c1) : 0.0f;                              \
    }                                                                       \
} while (0)

__global__ void __launch_bounds__(64)
crf_fwd_kernel(const float* __restrict__ em,
               const int*   __restrict__ tags,
               const float* __restrict__ mask,
               const float* __restrict__ trans,
               float* __restrict__ out)
{
    __shared__ float trs[Cn * Cn];
    __shared__ __align__(16) float p_sm[2][2][64];  // [warp][buf][slot]
    __shared__ float rsum[2];
    __shared__ int   slast;

    const int tid  = threadIdx.x;
    const int lane = tid & 31;
    const int w    = tid >> 5;
    const int b    = blockIdx.x * 2 + w;

    for (int i = tid; i < Cn * Cn; i += 64) trs[i] = trans[i];
    __syncthreads();

    const int  c0  = 2 * lane, c1 = 2 * lane + 1;
    const bool okA = (c0 < Cn), okB = (c1 < Cn);
    const float* emb = em + (size_t)b * Tn * Cn;
    const int*   tg  = tags + b * Tn;
    float* p_row = &p_sm[w][0][0];
    const unsigned pbase = (unsigned)__cvta_generic_to_shared(p_row);

    // ---- sequence length = sum(mask) ----
    float ms = 0.f;
    for (int i = lane; i < Tn; i += 32) ms += mask[b * Tn + i];
#pragma unroll
    for (int off = 16; off; off >>= 1) ms += __shfl_xor_sync(~0u, ms, off);
    const int tlim = (int)ms;   // steps run for t in [2, tlim)

    // ---- packed exp(transition) columns ----
    unsigned long long eA[28], eB[28];
#pragma unroll
    for (int k = 0; k < 28; k++) {
        int r0 = 2 * k, r1 = 2 * k + 1;
        float a0 = 0.f, a1 = 0.f, b0 = 0.f, b1 = 0.f;
        if (okA && r0 < Cn) a0 = __expf(trs[r0 * Cn + c0]);
        if (okA && r1 < Cn) a1 = __expf(trs[r1 * Cn + c0]);
        if (okB && r0 < Cn) b0 = __expf(trs[r0 * Cn + c1]);
        if (okB && r1 < Cn) b1 = __expf(trs[r1 * Cn + c1]);
        eA[k] = pack2(a0, a1);
        eB[k] = pack2(b0, b1);
    }

    // ---- init: p = exp(T[BOS,c] + em[b,1,c]), L = 0 ----
    float p0 = 0.f, p1 = 0.f;
    if (okA) p0 = __expf(trs[BOSi * Cn + c0] + emb[Cn + c0]);
    if (okB) p1 = __expf(trs[BOSi * Cn + c1] + emb[Cn + c1]);
    int buf = 0;
    *(float2*)(p_row + 2 * lane) = make_float2(p0, p1);
    __syncwarp();

    float L = 0.f;
    float emA0[4], emA1[4], emB0[4], emB1[4];

    LOADCHUNK(emA0, emA1, 2);
    int base = 2;
    for (;;) {
        if (base + 4 > tlim) break;
        LOADCHUNK(emB0, emB1, base + 4);
        CRF_STEP(emA0[0], emA1[0], true);
        CRF_STEP(emA0[1], emA1[1], false);
        CRF_STEP(emA0[2], emA1[2], false);
        CRF_STEP(emA0[3], emA1[3], false);
        base += 4;
        if (base + 4 > tlim) break;
        LOADCHUNK(emA0, emA1, base + 4);
        CRF_STEP(emB0[0], emB1[0], true);
        CRF_STEP(emB0[1], emB1[1], false);
        CRF_STEP(emB0[2], emB1[2], false);
        CRF_STEP(emB0[3], emB1[3], false);
        base += 4;
    }
    // scalar tail (< 4 steps), direct loads
    for (int t = base; t < tlim; t++) {
        float e0 = okA ? __ldg(emb + (size_t)t * Cn + c0) : 0.f;
        float e1 = okB ? __ldg(emb + (size_t)t * Cn + c1) : 0.f;
        CRF_STEP(e0, e1, false);
    }

    // ---- partition = L + log( sum_c p_c * exp(T[c,EOS]) ) ----
    float fA = 0.f, fB = 0.f;
    if (okA) fA = p0 * __expf(trs[c0 * Cn + EOSi]);
    if (okB) fB = p1 * __expf(trs[c1 * Cn + EOSi]);
    float tot = fA + fB;
#pragma unroll
    for (int off = 16; off; off >>= 1) tot += __shfl_xor_sync(~0u, tot, off);
    float partition = L + __logf(tot);

    // ---- gold-path score ----
    float s = 0.f;
    for (int t = 2 + lane; t < tlim; t += 32) {
        int a = tg[t - 1], c = tg[t];
        s += emb[(size_t)t * Cn + c] + trs[a * Cn + c];
    }
#pragma unroll
    for (int off = 16; off; off >>= 1) s += __shfl_xor_sync(~0u, s, off);

    if (lane == 0) {
        int   t1    = tg[1];
        float first = trs[BOSi * Cn + t1] + emb[Cn + t1];
        int   lt    = tg[tlim];  // tags at index == length
        float score = first + s + trs[lt * Cn + EOSi];
        g_partial[b] = partition - score;
    }

    // ---- fused reduction: last block to finish sums all partials ----
    __threadfence();
    __syncthreads();
    if (tid == 0) {
        unsigned tk = atomicAdd(&g_ticket, 1u);
        slast = (tk == (unsigned)(gridDim.x - 1)) ? 1 : 0;
    }
    __syncthreads();
    if (slast) {
        __threadfence();
        float acc = 0.f;
        for (int i = tid; i < Bn; i += 64) acc += __ldcg(&g_partial[i]);
#pragma unroll
        for (int off = 16; off; off >>= 1) acc += __shfl_xor_sync(~0u, acc, off);
        if (lane == 0) rsum[w] = acc;
        __syncthreads();
        if (tid == 0) {
            out[0] = rsum[0] + rsum[1];
            g_ticket = 0;   // reset for next graph replay
        }
    }
}

extern "C" void kernel_launch(void* const* d_in, const int* in_sizes, int n_in,
                              void* d_out, int out_size)
{
    const float* em    = (const float*)d_in[0];
    const int*   tags  = (const int*)  d_in[1];
    const float* mask  = (const float*)d_in[2];
    const float* trans = (const float*)d_in[3];
    float* out = (float*)d_out;

    crf_fwd_kernel<<<Bn / 2, 64>>>(em, tags, mask, trans, out);
}